// round 5
// baseline (speedup 1.0000x reference)
#include <cuda_runtime.h>
#include <cstdint>

// mean_aggregator: out[b,:] = (1/32) * sum_s emb[neighbors[b,s], :]
// B=50000, S=32, D=128, emb 500000x128 fp32 (256 MB > 126 MB L2).
//
// Phase 0: warp-bitonic sort of each row's 32 ids (ascending) -> scratch.
// Phases 1..3: fixed id-window passes (window ~85 MB, L2-resident per launch).
// Sorted ids make each window a contiguous run of positions: one ballot gives
// (start, cnt); inner loop does only cnt (~11) iterations of shfl+LDG+f32x2
// adds. Output partials RMW through L2 between passes.

#define THREADS 256
#define WARPS_PER_BLOCK (THREADS / 32)
#define NPASS 3

__device__ int g_sorted[1600000];   // 50000 * 32 ids

__global__ __launch_bounds__(THREADS)
void sort_rows_kernel(const int* __restrict__ neighbors, int batch)
{
    const int warp = (blockIdx.x * blockDim.x + threadIdx.x) >> 5;
    const int lane = threadIdx.x & 31;
    if (warp >= batch) return;

    int v = neighbors[warp * 32 + lane];

    #pragma unroll
    for (int k = 2; k <= 32; k <<= 1) {
        #pragma unroll
        for (int j = k >> 1; j > 0; j >>= 1) {
            const int other  = __shfl_xor_sync(0xffffffffu, v, j);
            const bool up    = ((lane & k) == 0);
            const bool lower = ((lane & j) == 0);
            v = ((lower == up) ? min(v, other) : max(v, other));
        }
    }

    g_sorted[warp * 32 + lane] = v;
}

__device__ __forceinline__ void add_f32x2(unsigned long long& a, float lo, float hi)
{
    unsigned long long b;
    asm("mov.b64 %0, {%1, %2};" : "=l"(b) : "f"(lo), "f"(hi));
    asm("add.rn.f32x2 %0, %1, %2;" : "=l"(a) : "l"(a), "l"(b));
}

__global__ __launch_bounds__(THREADS)
void mean_agg_pass(const float4* __restrict__ emb,   // [N, 32] float4
                   float4* __restrict__ out,         // [B, 32] float4
                   int batch, int lo, int hi, int pass)
{
    const int warp = (blockIdx.x * blockDim.x + threadIdx.x) >> 5;
    const int lane = threadIdx.x & 31;
    if (warp >= batch) return;

    // Lane l = sorted id at position l of this row.
    const int sid = g_sorted[warp * 32 + lane];

    const bool in_win = ((unsigned)(sid - lo)) < ((unsigned)(hi - lo));
    const unsigned m  = __ballot_sync(0xffffffffu, in_win);
    const int cnt     = __popc(m);
    const int start   = __ffs(m) - 1;          // valid when cnt > 0

    unsigned long long acc01, acc23;           // packed f32x2 accumulators
    if (pass == 0) {
        acc01 = 0ull;
        acc23 = 0ull;
    } else {
        const float4 p = out[(size_t)warp * 32 + lane];
        asm("mov.b64 %0, {%1, %2};" : "=l"(acc01) : "f"(p.x), "f"(p.y));
        asm("mov.b64 %0, {%1, %2};" : "=l"(acc23) : "f"(p.z), "f"(p.w));
    }

    #pragma unroll 4
    for (int i = 0; i < cnt; ++i) {
        const int n = __shfl_sync(0xffffffffu, sid, start + i);
        const float4 v = __ldg(&emb[(size_t)n * 32 + lane]);
        add_f32x2(acc01, v.x, v.y);
        add_f32x2(acc23, v.z, v.w);
    }

    float4 r;
    asm("mov.b64 {%0, %1}, %2;" : "=f"(r.x), "=f"(r.y) : "l"(acc01));
    asm("mov.b64 {%0, %1}, %2;" : "=f"(r.z), "=f"(r.w) : "l"(acc23));

    if (pass == NPASS - 1) {
        const float inv = 1.0f / 32.0f;
        r.x *= inv; r.y *= inv; r.z *= inv; r.w *= inv;
    }

    out[(size_t)warp * 32 + lane] = r;
}

extern "C" void kernel_launch(void* const* d_in, const int* in_sizes, int n_in,
                              void* d_out, int out_size)
{
    const int* neighbors = (const int*)d_in[0];     // [B, 32] int32
    const float4* emb    = (const float4*)d_in[1];  // [N, 128] fp32 as float4

    const int batch     = in_sizes[0] / 32;         // 50000
    const int num_nodes = in_sizes[1] / 128;        // 500000

    const int blocks = (batch + WARPS_PER_BLOCK - 1) / WARPS_PER_BLOCK;

    sort_rows_kernel<<<blocks, THREADS>>>(neighbors, batch);

    for (int p = 0; p < NPASS; ++p) {
        const int lo = (int)(((long long)num_nodes * p) / NPASS);
        const int hi = (p == NPASS - 1)
                         ? num_nodes
                         : (int)(((long long)num_nodes * (p + 1)) / NPASS);
        mean_agg_pass<<<blocks, THREADS>>>(emb, (float4*)d_out,
                                           batch, lo, hi, p);
    }
}